// round 4
// baseline (speedup 1.0000x reference)
#include <cuda_runtime.h>
#include <cstdint>

#define BB 256
#define TT 1024
#define EE 32
#define HH 64
#define GG 256          // 4*H
#define VV 96
#define NROWS (BB*TT)   // 262144
#define NLOGITS (NROWS*VV)

typedef unsigned long long u64;

// ---------------- scratch (device globals: no allocation allowed) ----------
// Thread j (0..127): w=j>>5, l=j&31, m=l&15, sel=(l>>4)&1, u=16*w+m.
//   sel=0: gate rows (i[u], g[u])  = (u,     128+u)
//   sel=1: gate rows (f[u], o[u])  = (64+u,  192+u)
__device__ float2 g_projP[VV][128];               // paired (W_ih@emb[v] + b_ih + b_hh)
__device__ float2 g_W2[128][HH];                  // paired W_hh rows per thread j
__device__ float  g_hseq[(size_t)NROWS * HH];     // 64 MB hidden-state sequence
__device__ double g_loss;

// ---------------- f32x2 helpers -------------------------------------------
__device__ __forceinline__ void ffma2(u64 &d, u64 a, u64 b) {
    asm("fma.rn.f32x2 %0, %1, %2, %0;" : "+l"(d) : "l"(a), "l"(b));
}
__device__ __forceinline__ u64 fadd2(u64 a, u64 b) {
    u64 d; asm("add.rn.f32x2 %0, %1, %2;" : "=l"(d) : "l"(a), "l"(b)); return d;
}
__device__ __forceinline__ u64 f2_dup(float x) {
    u64 r; asm("mov.b64 %0, {%1, %1};" : "=l"(r) : "f"(x)); return r;
}
__device__ __forceinline__ void f2_unpack(u64 v, float &a, float &b) {
    asm("mov.b64 {%0, %1}, %2;" : "=f"(a), "=f"(b) : "l"(v));
}

__device__ __forceinline__ float sigm(float x)   { return 1.0f / (1.0f + __expf(-x)); }
__device__ __forceinline__ float tanh_a(float x) { return 1.0f - 2.0f / (1.0f + __expf(2.0f * x)); }

// thread j -> paired gate rows
__device__ __host__ __forceinline__ void rows_of(int j, int &ra, int &rb) {
    int w = j >> 5, l = j & 31, m = l & 15, sel = (l >> 4) & 1;
    int u = 16 * w + m;
    ra = 64 * sel + u;
    rb = ra + 128;
}

// ---------------- kernel 1: prep ------------------------------------------
__global__ void prep_kernel(const float* __restrict__ emb, const float* __restrict__ W_ih,
                            const float* __restrict__ W_hh, const float* __restrict__ b_ih,
                            const float* __restrict__ b_hh)
{
    int t = blockIdx.x * blockDim.x + threadIdx.x;
    if (t < VV * 128) {
        int v = t >> 7, j = t & 127;
        int ra, rb; rows_of(j, ra, rb);
        float sa = b_ih[ra] + b_hh[ra];
        float sb = b_ih[rb] + b_hh[rb];
        #pragma unroll
        for (int e = 0; e < EE; e++) {
            float ev = emb[v * EE + e];
            sa += W_ih[ra * EE + e] * ev;
            sb += W_ih[rb * EE + e] * ev;
        }
        g_projP[v][j] = make_float2(sa, sb);
    }
    if (t < 128 * HH) {
        int j = t >> 6, k = t & 63;
        int ra, rb; rows_of(j, ra, rb);
        g_W2[j][k] = make_float2(W_hh[ra * HH + k], W_hh[rb * HH + k]);
    }
    if (t == 0) g_loss = 0.0;
}

// ---------------- kernel 2: LSTM scan (critical path) ----------------------
// 128 blocks x 128 threads; block handles TWO batch lanes in the SAME threads
// (in-thread interleave -> cross-lane ILP fills all stalls; W regs shared).
// Double-buffered h -> single __syncthreads per step. p=sigm(i)*tanh(g)
// crosses from lane l to l+16 via shfl (no smem round trip).
__global__ __launch_bounds__(128) void lstm_kernel(const int* __restrict__ idx)
{
    __shared__ __align__(16) u64 sh_h[2][2][HH];  // [buf][lane][unit], dup pairs
    __shared__ int sh_idx[2][TT];

    int j = threadIdx.x;
    int l = j & 31, m = l & 15, sel = (l >> 4) & 1;
    int u = 16 * (j >> 5) + m;
    int bA = blockIdx.x * 2;

    // stage both idx rows (2048 contiguous ints)
    {
        const int4* src = (const int4*)(idx + (size_t)bA * TT);
        int4* dst = (int4*)sh_idx;
        #pragma unroll
        for (int i = j; i < 2 * TT / 4; i += 128) dst[i] = src[i];
    }

    // weights: 64 x u64 = 128 regs, shared by both lanes
    u64 w[HH];
    {
        const u64* wp = (const u64*)g_W2[j];
        #pragma unroll
        for (int k = 0; k < HH; k++) w[k] = wp[k];
    }
    if (j < HH) { sh_h[0][0][j] = 0ull; sh_h[0][1][j] = 0ull; }

    float cA = 0.f, cB = 0.f;
    // uniform activation for the second gate: a = A*sigm(S*x)+D  (tanh=2*sigm(2x)-1)
    float Sg = sel ? 1.f : 2.f;
    float Ag = sel ? 1.f : 2.f;
    float Dg = sel ? 0.f : -1.f;
    float* houtA = g_hseq + (size_t)bA * TT * HH + u;
    float* houtB = houtA + (size_t)TT * HH;

    __syncthreads();

    u64 xpA = *(const u64*)&g_projP[sh_idx[0][0]][j];
    u64 xpB = *(const u64*)&g_projP[sh_idx[1][0]][j];

    for (int t = 0; t < TT; t++) {
        int tn = (t + 1 < TT) ? (t + 1) : (TT - 1);
        u64 pfA = *(const u64*)&g_projP[sh_idx[0][tn]][j];
        u64 pfB = *(const u64*)&g_projP[sh_idx[1][tn]][j];

        const ulonglong2* hA4 = (const ulonglong2*)sh_h[t & 1][0];
        const ulonglong2* hB4 = (const ulonglong2*)sh_h[t & 1][1];

        u64 aA0 = xpA, aA1 = 0ull, aB0 = xpB, aB1 = 0ull;
        #pragma unroll
        for (int kk = 0; kk < 16; kk++) {
            ulonglong2 hA2 = hA4[2 * kk];
            ulonglong2 hA3 = hA4[2 * kk + 1];
            ulonglong2 hB2 = hB4[2 * kk];
            ulonglong2 hB3 = hB4[2 * kk + 1];
            ffma2(aA0, hA2.x, w[4 * kk]);
            ffma2(aB0, hB2.x, w[4 * kk]);
            ffma2(aA1, hA2.y, w[4 * kk + 1]);
            ffma2(aB1, hB2.y, w[4 * kk + 1]);
            ffma2(aA0, hA3.x, w[4 * kk + 2]);
            ffma2(aB0, hB3.x, w[4 * kk + 2]);
            ffma2(aA1, hA3.y, w[4 * kk + 3]);
            ffma2(aB1, hB3.y, w[4 * kk + 3]);
        }
        u64 gA = fadd2(aA0, aA1);
        u64 gB = fadd2(aB0, aB1);
        float gAlo, gAhi, gBlo, gBhi;
        f2_unpack(gA, gAlo, gAhi);
        f2_unpack(gB, gBlo, gBhi);

        float fiA = sigm(gAlo);                        // i (sel=0) or f (sel=1)
        float fiB = sigm(gBlo);
        float goA = fmaf(Ag, sigm(Sg * gAhi), Dg);     // tanh(g) or sigm(o)
        float goB = fmaf(Ag, sigm(Sg * gBhi), Dg);

        float pA = fiA * goA;                          // sigm(i)*tanh(g) (sel=0 lanes)
        float pB = fiB * goB;
        float prA = __shfl_up_sync(0xffffffffu, pA, 16);
        float prB = __shfl_up_sync(0xffffffffu, pB, 16);

        if (sel) {                                     // updater half-lanes
            cA = fmaf(fiA, cA, prA);                   // c = f*c + i*g
            cB = fmaf(fiB, cB, prB);
            float hA = goA * tanh_a(cA);               // h = o*tanh(c)
            float hB = goB * tanh_a(cB);
            sh_h[(t + 1) & 1][0][u] = f2_dup(hA);
            sh_h[(t + 1) & 1][1][u] = f2_dup(hB);
            houtA[(size_t)t * HH] = hA;
            houtB[(size_t)t * HH] = hB;
        }
        __syncthreads();
        xpA = pfA;
        xpB = pfB;
    }
}

// ---------------- kernel 3: output projection + log-softmax loss -----------
__global__ __launch_bounds__(256) void outproj_kernel(const float* __restrict__ fc_w,
                                                      const float* __restrict__ fc_b,
                                                      const int*   __restrict__ targets,
                                                      float*       __restrict__ out)
{
    __shared__ float wS[HH][97];                  // wS[k][v] = fc_w[v][k]
    __shared__ __align__(16) float hS[HH][66];    // hS[k][r]
    __shared__ float bS[VV];

    int tid = threadIdx.x;
    for (int i = tid; i < VV * HH; i += 256) { int v = i >> 6, k = i & 63; wS[k][v] = fc_w[i]; }
    if (tid < VV) bS[tid] = fc_b[tid];

    int rbase = blockIdx.x * 64;
    for (int i4 = tid; i4 < 64 * 16; i4 += 256) {
        int r = i4 >> 4, k4 = (i4 & 15) << 2;
        float4 hv = *(const float4*)&g_hseq[((size_t)(rbase + r)) * HH + k4];
        hS[k4][r] = hv.x; hS[k4 + 1][r] = hv.y; hS[k4 + 2][r] = hv.z; hS[k4 + 3][r] = hv.w;
    }
    __syncthreads();

    int tc = tid & 31, tr = tid >> 5;
    int c0 = 3 * tc;

    u64 acc[4][3];
    #pragma unroll
    for (int p = 0; p < 4; p++)
        #pragma unroll
        for (int q = 0; q < 3; q++) acc[p][q] = 0ull;

    #pragma unroll 4
    for (int k = 0; k < HH; k++) {
        u64 b0 = f2_dup(wS[k][c0]);
        u64 b1 = f2_dup(wS[k][c0 + 1]);
        u64 b2 = f2_dup(wS[k][c0 + 2]);
        #pragma unroll
        for (int p = 0; p < 4; p++) {
            u64 a = *(const u64*)&hS[k][(tr * 4 + p) * 2];
            ffma2(acc[p][0], a, b0);
            ffma2(acc[p][1], a, b1);
            ffma2(acc[p][2], a, b2);
        }
    }

    float lg[8][3];
    #pragma unroll
    for (int p = 0; p < 4; p++)
        #pragma unroll
        for (int q = 0; q < 3; q++) {
            float lo, hi; f2_unpack(acc[p][q], lo, hi);
            lg[2 * p][q]     = lo + bS[c0 + q];
            lg[2 * p + 1][q] = hi + bS[c0 + q];
        }

    float lacc = 0.f;
    #pragma unroll
    for (int rr = 0; rr < 8; rr++) {
        int row = tr * 8 + rr;
        float v0 = lg[rr][0], v1 = lg[rr][1], v2 = lg[rr][2];
        float* gout = out + (size_t)(rbase + row) * VV + c0;
        gout[0] = v0; gout[1] = v1; gout[2] = v2;

        float mx = fmaxf(v0, fmaxf(v1, v2));
        #pragma unroll
        for (int off = 16; off; off >>= 1) mx = fmaxf(mx, __shfl_xor_sync(0xffffffffu, mx, off));
        float s = __expf(v0 - mx) + __expf(v1 - mx) + __expf(v2 - mx);
        #pragma unroll
        for (int off = 16; off; off >>= 1) s += __shfl_xor_sync(0xffffffffu, s, off);

        int tgt = targets[rbase + row];
        bool own = (tgt >= c0) && (tgt < c0 + 3);
        float lt = (tgt == c0) ? v0 : ((tgt == c0 + 1) ? v1 : v2);
        lacc += own ? (mx + __logf(s) - lt) : 0.f;
    }
    #pragma unroll
    for (int off = 16; off; off >>= 1) lacc += __shfl_xor_sync(0xffffffffu, lacc, off);
    if (tc == 0) atomicAdd(&g_loss, (double)lacc);
}

__global__ void loss_fin_kernel(float* __restrict__ out)
{
    out[NLOGITS] = (float)(g_loss * (1.0 / (double)NROWS));
}

// ---------------- launch ----------------------------------------------------
extern "C" void kernel_launch(void* const* d_in, const int* in_sizes, int n_in,
                              void* d_out, int out_size)
{
    const int*   idx     = (const int*)  d_in[0];
    const int*   targets = (const int*)  d_in[1];
    const float* emb     = (const float*)d_in[2];
    const float* W_ih    = (const float*)d_in[3];
    const float* W_hh    = (const float*)d_in[4];
    const float* b_ih    = (const float*)d_in[5];
    const float* b_hh    = (const float*)d_in[6];
    const float* fc_w    = (const float*)d_in[7];
    const float* fc_b    = (const float*)d_in[8];
    float* out = (float*)d_out;

    prep_kernel<<<96, 256>>>(emb, W_ih, W_hh, b_ih, b_hh);
    lstm_kernel<<<BB / 2, 128>>>(idx);
    outproj_kernel<<<NROWS / 64, 256>>>(fc_w, fc_b, targets, out);
    if (out_size > NLOGITS) loss_fin_kernel<<<1, 1>>>(out);
}

// round 5
// speedup vs baseline: 1.9024x; 1.9024x over previous
#include <cuda_runtime.h>
#include <cstdint>

#define BB 256
#define TT 1024
#define EE 32
#define HH 64
#define GG 256          // 4*H
#define VV 96
#define NROWS (BB*TT)   // 262144
#define NLOGITS (NROWS*VV)

typedef unsigned long long u64;

// ---------------- scratch (device globals: no allocation allowed) ----------
// Thread j (0..127): w=j>>5, l=j&31, m=l&15, sel=(l>>4)&1, u=16*w+m.
//   sel=0: gate rows (i[u], g[u])  = (u,     128+u)
//   sel=1: gate rows (f[u], o[u])  = (64+u,  192+u)
__device__ float2 g_projP[VV][128];               // paired (W_ih@emb[v] + b_ih + b_hh)
__device__ float2 g_W2[128][HH];                  // paired W_hh rows per thread j
__device__ float  g_hseq[(size_t)NROWS * HH];     // 64 MB hidden-state sequence
__device__ double g_loss;

// ---------------- f32x2 helpers -------------------------------------------
__device__ __forceinline__ void ffma2(u64 &d, u64 a, u64 b) {
    asm("fma.rn.f32x2 %0, %1, %2, %0;" : "+l"(d) : "l"(a), "l"(b));
}
__device__ __forceinline__ u64 fadd2(u64 a, u64 b) {
    u64 d; asm("add.rn.f32x2 %0, %1, %2;" : "=l"(d) : "l"(a), "l"(b)); return d;
}
__device__ __forceinline__ u64 f2_dup(float x) {
    u64 r; asm("mov.b64 %0, {%1, %1};" : "=l"(r) : "f"(x)); return r;
}
__device__ __forceinline__ void f2_unpack(u64 v, float &a, float &b) {
    asm("mov.b64 {%0, %1}, %2;" : "=f"(a), "=f"(b) : "l"(v));
}

// fast tanh via MUFU.TANH (single 16-cyc MUFU; accurate in the |x|<~1 regime
// this data lives in)
__device__ __forceinline__ float tanh_f(float x) {
    float r; asm("tanh.approx.f32 %0, %1;" : "=f"(r) : "f"(x)); return r;
}
// precise fallbacks for non-critical kernels
__device__ __forceinline__ float sigm(float x)   { return 1.0f / (1.0f + __expf(-x)); }

// thread j -> paired gate rows
__device__ __host__ __forceinline__ void rows_of(int j, int &ra, int &rb) {
    int w = j >> 5, l = j & 31, m = l & 15, sel = (l >> 4) & 1;
    int u = 16 * w + m;
    ra = 64 * sel + u;
    rb = ra + 128;
}

// ---------------- kernel 1: prep ------------------------------------------
__global__ void prep_kernel(const float* __restrict__ emb, const float* __restrict__ W_ih,
                            const float* __restrict__ W_hh, const float* __restrict__ b_ih,
                            const float* __restrict__ b_hh)
{
    int t = blockIdx.x * blockDim.x + threadIdx.x;
    if (t < VV * 128) {
        int v = t >> 7, j = t & 127;
        int ra, rb; rows_of(j, ra, rb);
        float sa = b_ih[ra] + b_hh[ra];
        float sb = b_ih[rb] + b_hh[rb];
        #pragma unroll
        for (int e = 0; e < EE; e++) {
            float ev = emb[v * EE + e];
            sa += W_ih[ra * EE + e] * ev;
            sb += W_ih[rb * EE + e] * ev;
        }
        g_projP[v][j] = make_float2(sa, sb);
    }
    if (t < 128 * HH) {
        int j = t >> 6, k = t & 63;
        int ra, rb; rows_of(j, ra, rb);
        g_W2[j][k] = make_float2(W_hh[ra * HH + k], W_hh[rb * HH + k]);
    }
    if (t == 0) g_loss = 0.0;
}

// ---------------- kernel 2: LSTM scan (critical path) ----------------------
// 256 blocks x 128 threads, one batch lane per block (2 warps/SMSP when two
// blocks co-reside -> latency hiding). Thread j owns gate rows (ra, rb) as one
// f32x2 chain vs W pairs in 128 regs. h double-buffered as duplicated f32x2 in
// SMEM -> one __syncthreads per step. p = sigm(i)*tanh(g) crosses lanes via
// shfl. All activations = A*tanh(S*x)+D (warp-uniform, 1 MUFU each).
__global__ __launch_bounds__(128) void lstm_kernel(const int* __restrict__ idx)
{
    __shared__ __align__(16) u64 sh_h[2][HH];     // double-buffered dup pairs
    __shared__ int sh_idx[TT];

    int j = threadIdx.x;                          // 0..127
    int l = j & 31, m = l & 15, sel = (l >> 4) & 1;
    int u = 16 * (j >> 5) + m;
    int b = blockIdx.x;

    // stage idx row in smem (coalesced, once)
    {
        const int4* src = (const int4*)(idx + (size_t)b * TT);
        int4* dst = (int4*)sh_idx;
        #pragma unroll
        for (int i = j; i < TT / 4; i += 128) dst[i] = src[i];
    }

    // weights into registers (64 x u64 = 128 regs)
    u64 w[HH];
    {
        const u64* wp = (const u64*)g_W2[j];
        #pragma unroll
        for (int k = 0; k < HH; k++) w[k] = wp[k];
    }
    if (j < HH) sh_h[0][j] = 0ull;

    float cst = 0.f;                              // cell state (sel=1 lanes)
    // first act: sigma(x) = 0.5 + 0.5*tanh(0.5x) for both halves (i or f)
    // second act: sel=0 -> tanh(g): S=1,A=1,D=0 ; sel=1 -> sigma(o): S=A=D=0.5
    float Sg = sel ? 0.5f : 1.0f;
    float Ag = sel ? 0.5f : 1.0f;
    float Dg = sel ? 0.5f : 0.0f;
    float* hout = g_hseq + (size_t)b * TT * HH + u;

    __syncthreads();

    u64 xp_cur = *(const u64*)&g_projP[sh_idx[0]][j];

    for (int t = 0; t < TT; t++) {
        int tn = (t + 1 < TT) ? (t + 1) : (TT - 1);
        u64 xp_pf = *(const u64*)&g_projP[sh_idx[tn]][j];   // L2-resident table

        // gate pre-activations: xp + sum_k h[k]*w[k]  (4 FFMA2 chains)
        u64 a0 = xp_cur, a1 = 0ull, a2 = 0ull, a3 = 0ull;
        const ulonglong2* h4 = (const ulonglong2*)sh_h[t & 1];
        #pragma unroll
        for (int kk = 0; kk < 16; kk++) {
            ulonglong2 ha = h4[2 * kk];           // LDS.128 broadcast
            ulonglong2 hb = h4[2 * kk + 1];
            ffma2(a0, ha.x, w[4 * kk]);
            ffma2(a1, ha.y, w[4 * kk + 1]);
            ffma2(a2, hb.x, w[4 * kk + 2]);
            ffma2(a3, hb.y, w[4 * kk + 3]);
        }
        u64 gsum = fadd2(fadd2(a0, a1), fadd2(a2, a3));
        float glo, ghi; f2_unpack(gsum, glo, ghi);

        float fi = fmaf(0.5f, tanh_f(0.5f * glo), 0.5f);    // sigm: i (sel=0) / f (sel=1)
        float go = fmaf(Ag, tanh_f(Sg * ghi), Dg);          // tanh(g) / sigm(o)

        float p  = fi * go;                                 // sigm(i)*tanh(g) on sel=0
        float pr = __shfl_up_sync(0xffffffffu, p, 16);

        if (sel) {
            cst = fmaf(fi, cst, pr);                        // c = f*c + i*g
            float h = go * tanh_f(cst);                     // h = o*tanh(c)
            sh_h[(t + 1) & 1][u] = f2_dup(h);
            hout[(size_t)t * HH] = h;                       // coalesced 256B/step
        }
        __syncthreads();
        xp_cur = xp_pf;
    }
}

// ---------------- kernel 3: output projection + log-softmax loss -----------
__global__ __launch_bounds__(256) void outproj_kernel(const float* __restrict__ fc_w,
                                                      const float* __restrict__ fc_b,
                                                      const int*   __restrict__ targets,
                                                      float*       __restrict__ out)
{
    __shared__ float wS[HH][97];                  // wS[k][v] = fc_w[v][k]
    __shared__ __align__(16) float hS[HH][66];    // hS[k][r]
    __shared__ float bS[VV];

    int tid = threadIdx.x;
    for (int i = tid; i < VV * HH; i += 256) { int v = i >> 6, k = i & 63; wS[k][v] = fc_w[i]; }
    if (tid < VV) bS[tid] = fc_b[tid];

    int rbase = blockIdx.x * 64;
    for (int i4 = tid; i4 < 64 * 16; i4 += 256) {
        int r = i4 >> 4, k4 = (i4 & 15) << 2;
        float4 hv = *(const float4*)&g_hseq[((size_t)(rbase + r)) * HH + k4];
        hS[k4][r] = hv.x; hS[k4 + 1][r] = hv.y; hS[k4 + 2][r] = hv.z; hS[k4 + 3][r] = hv.w;
    }
    __syncthreads();

    int tc = tid & 31, tr = tid >> 5;
    int c0 = 3 * tc;

    u64 acc[4][3];
    #pragma unroll
    for (int p = 0; p < 4; p++)
        #pragma unroll
        for (int q = 0; q < 3; q++) acc[p][q] = 0ull;

    #pragma unroll 4
    for (int k = 0; k < HH; k++) {
        u64 b0 = f2_dup(wS[k][c0]);
        u64 b1 = f2_dup(wS[k][c0 + 1]);
        u64 b2 = f2_dup(wS[k][c0 + 2]);
        #pragma unroll
        for (int p = 0; p < 4; p++) {
            u64 a = *(const u64*)&hS[k][(tr * 4 + p) * 2];
            ffma2(acc[p][0], a, b0);
            ffma2(acc[p][1], a, b1);
            ffma2(acc[p][2], a, b2);
        }
    }

    float lg[8][3];
    #pragma unroll
    for (int p = 0; p < 4; p++)
        #pragma unroll
        for (int q = 0; q < 3; q++) {
            float lo, hi; f2_unpack(acc[p][q], lo, hi);
            lg[2 * p][q]     = lo + bS[c0 + q];
            lg[2 * p + 1][q] = hi + bS[c0 + q];
        }

    float lacc = 0.f;
    #pragma unroll
    for (int rr = 0; rr < 8; rr++) {
        int row = tr * 8 + rr;
        float v0 = lg[rr][0], v1 = lg[rr][1], v2 = lg[rr][2];
        float* gout = out + (size_t)(rbase + row) * VV + c0;
        gout[0] = v0; gout[1] = v1; gout[2] = v2;

        float mx = fmaxf(v0, fmaxf(v1, v2));
        #pragma unroll
        for (int off = 16; off; off >>= 1) mx = fmaxf(mx, __shfl_xor_sync(0xffffffffu, mx, off));
        float s = __expf(v0 - mx) + __expf(v1 - mx) + __expf(v2 - mx);
        #pragma unroll
        for (int off = 16; off; off >>= 1) s += __shfl_xor_sync(0xffffffffu, s, off);

        int tgt = targets[rbase + row];
        bool own = (tgt >= c0) && (tgt < c0 + 3);
        float lt = (tgt == c0) ? v0 : ((tgt == c0 + 1) ? v1 : v2);
        lacc += own ? (mx + __logf(s) - lt) : 0.f;
    }
    #pragma unroll
    for (int off = 16; off; off >>= 1) lacc += __shfl_xor_sync(0xffffffffu, lacc, off);
    if (tc == 0) atomicAdd(&g_loss, (double)lacc);
}

__global__ void loss_fin_kernel(float* __restrict__ out)
{
    out[NLOGITS] = (float)(g_loss * (1.0 / (double)NROWS));
}

// ---------------- launch ----------------------------------------------------
extern "C" void kernel_launch(void* const* d_in, const int* in_sizes, int n_in,
                              void* d_out, int out_size)
{
    const int*   idx     = (const int*)  d_in[0];
    const int*   targets = (const int*)  d_in[1];
    const float* emb     = (const float*)d_in[2];
    const float* W_ih    = (const float*)d_in[3];
    const float* W_hh    = (const float*)d_in[4];
    const float* b_ih    = (const float*)d_in[5];
    const float* b_hh    = (const float*)d_in[6];
    const float* fc_w    = (const float*)d_in[7];
    const float* fc_b    = (const float*)d_in[8];
    float* out = (float*)d_out;

    prep_kernel<<<96, 256>>>(emb, W_ih, W_hh, b_ih, b_hh);
    lstm_kernel<<<BB, 128>>>(idx);
    outproj_kernel<<<NROWS / 64, 256>>>(fc_w, fc_b, targets, out);
    if (out_size > NLOGITS) loss_fin_kernel<<<1, 1>>>(out);
}